// round 16
// baseline (speedup 1.0000x reference)
#include <cuda_runtime.h>
#include <math.h>

#define IMG 512
#define BS  32
#define OH  255
#define OW  255
#define TC  32      // cells per tile dim (tile = 64x64 output pixels)
#define NPY 33      // patch rows per tile
#define NPXP 17     // horizontal patch PAIRS per tile
#define NUNIT (NPY * NPXP)   // 561
#define SIMW 34     // sim row stride (even -> float2 stores aligned)

typedef unsigned long long ull;

// packed/pre-scaled weights (layout below)
__constant__ __align__(8) float cbuf[172];
__device__ __align__(8) float g_stage[172];

// Layout (float offsets):
//   0: W1p  (32 float2) [q*4+j] = (W1[2q][j],   W1[2q+1][j])   <- read via SMEM
//  64: b1p  ( 4 float2) [j]     = (b1[j], 0)                   <- read via SMEM
//  72: W2s  (16 float ) 0.5*W2                                 <- constant port
//  88: b2   ( 4 float )                                        <- constant port
//  92: W3p  (32 float2) [j*8+i] = 0.5*(W3[j][2i], W3[j][2i+1]) <- constant port
// 156: b3p  ( 8 float2) [i]     = (b3[2i], b3[2i+1])           <- constant port
__global__ void prep_kernel(const float* __restrict__ W1, const float* __restrict__ b1,
                            const float* __restrict__ W2, const float* __restrict__ b2,
                            const float* __restrict__ W3, const float* __restrict__ b3) {
    int f = threadIdx.x;
    if (f >= 172) return;
    float v;
    if (f < 64) {
        int q = f >> 1, lane = f & 1;
        int p = q >> 2, j = q & 3;
        v = W1[(2 * p + lane) * 4 + j];
    } else if (f < 72) {
        int q = (f - 64) >> 1, lane = f & 1;
        v = lane ? 0.0f : b1[q];
    } else if (f < 88) {
        v = 0.5f * W2[f - 72];
    } else if (f < 92) {
        v = b2[f - 88];
    } else if (f < 156) {
        int q = (f - 92) >> 1, lane = f & 1;
        int j = q >> 3, i = q & 7;
        v = 0.5f * W3[j * 16 + 2 * i + lane];
    } else {
        int q = (f - 156) >> 1, lane = f & 1;
        v = b3[2 * q + lane];
    }
    g_stage[f] = v;
}

__device__ __forceinline__ ull pk(float lo, float hi) {
    ull r; asm("mov.b64 %0, {%1, %2};" : "=l"(r) : "f"(lo), "f"(hi)); return r;
}
__device__ __forceinline__ void upk(ull v, float& lo, float& hi) {
    asm("mov.b64 {%0, %1}, %2;" : "=f"(lo), "=f"(hi) : "l"(v));
}
__device__ __forceinline__ ull fma2(ull a, ull b, ull c) {
    ull d; asm("fma.rn.f32x2 %0, %1, %2, %3;" : "=l"(d) : "l"(a), "l"(b), "l"(c)); return d;
}
__device__ __forceinline__ ull add2(ull a, ull b) {
    ull d; asm("add.rn.f32x2 %0, %1, %2;" : "=l"(d) : "l"(a), "l"(b)); return d;
}
// single-instruction MUFU.RSQ (operands clamped well inside range; ~2^-22 rel err)
__device__ __forceinline__ float rsqrt_ap(float x) {
    float y; asm("rsqrt.approx.f32 %0, %1;" : "=f"(y) : "f"(x)); return y;
}

__global__ __launch_bounds__(256, 4)
void fused_kernel(const float* __restrict__ img, float* __restrict__ out) {
    __shared__ float sim[NPY * SIMW];        // 33 rows x 34 floats
    __shared__ __align__(8) float swt[72];   // W1p + b1p via LDS broadcast port

    const int t  = threadIdx.x;
    const int b0 = blockIdx.x * TC;
    const int a0 = blockIdx.y * TC;
    const int bt = blockIdx.z;
    const float* imgb = img + (size_t)bt * (IMG * IMG);
    const ull* imgu = reinterpret_cast<const ull*>(imgb);

    // stage the layer-1 weight stream into smem: splits weight fetches
    // across the constant port (W2/W3) and the smem port (W1) so the two
    // drain concurrently instead of serializing on the LDC port.
    if (t < 72) swt[t] = g_stage[t];
    __syncthreads();

    const ull* W1p = reinterpret_cast<const ull*>(swt);        // smem port
    const ull* b1p = reinterpret_cast<const ull*>(swt + 64);   // smem port
    const float* W2s = cbuf + 72;                              // constant port
    const float* b2  = cbuf + 88;
    const ull* W3p = reinterpret_cast<const ull*>(cbuf + 92);
    const ull* b3p = reinterpret_cast<const ull*>(cbuf + 156);

    // ---- patch-PAIR phase: two horizontally adjacent patches per unit,
    // sharing the middle 2-column strip and every weight fetch.
    for (int u = t; u < NUNIT; u += 256) {
        const int pyy = u / NPXP;            // 0..32
        const int pxp = u - pyy * NPXP;      // 0..16
        const int oy  = a0 - 1 + pyy;
        const int ox0 = b0 - 1 + 2 * pxp;    // left patch col; right = ox0+1

        const int ry = min(max(oy, 0), OH - 1);
        const int ua = min(max(ox0, 0), 255);
        const int ub = min(ox0 + 1, 255);
        const int uc = min(ox0 + 2, 255);
        const bool v0 = ((unsigned)oy < OH) & ((unsigned)ox0 < OW);
        const bool v1 = ((unsigned)oy < OH) & ((unsigned)(ox0 + 1) < OW);

        const ull* row = imgu + (size_t)(2 * ry) * (IMG / 2);
        ull A[4], B[4], C[4];                // strips: P0=(A,B), P1=(B,C)
#pragma unroll
        for (int r = 0; r < 4; r++) {
            const ull* rp = row + (size_t)r * (IMG / 2);
            A[r] = __ldg(rp + ua);
            B[r] = __ldg(rp + ub);
            C[r] = __ldg(rp + uc);
        }

        // nx2 for both patches; middle strip squared once
        ull na = 0ULL, nb = 0ULL, nc = 0ULL;
#pragma unroll
        for (int r = 0; r < 4; r++) {
            na = fma2(A[r], A[r], na);
            nb = fma2(B[r], B[r], nb);
            nc = fma2(C[r], C[r], nc);
        }
        const ull nx0p = add2(na, nb);
        const ull nx1p = add2(nb, nc);

        // layer 1 for both patches, weights via SMEM broadcast
        ull acc0[4], acc1[4];
#pragma unroll
        for (int j = 0; j < 4; j++) { acc0[j] = b1p[j]; acc1[j] = b1p[j]; }
#pragma unroll
        for (int r = 0; r < 4; r++) {
#pragma unroll
            for (int j = 0; j < 4; j++) {
                ull wL = W1p[(2 * r) * 4 + j];
                ull wR = W1p[(2 * r + 1) * 4 + j];
                acc0[j] = fma2(A[r], wL, acc0[j]);
                acc0[j] = fma2(B[r], wR, acc0[j]);
                acc1[j] = fma2(B[r], wL, acc1[j]);
                acc1[j] = fma2(C[r], wR, acc1[j]);
            }
        }
        float h0[4], h1[4];
#pragma unroll
        for (int j = 0; j < 4; j++) {
            float lo, hi;
            upk(acc0[j], lo, hi); float s0v = lo + hi; h0[j] = s0v + fabsf(s0v);
            upk(acc1[j], lo, hi); float s1v = lo + hi; h1[j] = s1v + fabsf(s1v);
        }

        // layer 2 for both patches (W2s = 0.5*W2), constant port
        float g0[4], g1[4];
#pragma unroll
        for (int j = 0; j < 4; j++) { g0[j] = b2[j]; g1[j] = b2[j]; }
#pragma unroll
        for (int i = 0; i < 4; i++)
#pragma unroll
            for (int j = 0; j < 4; j++) {
                float w = W2s[i * 4 + j];
                g0[j] = fmaf(h0[i], w, g0[j]);
                g1[j] = fmaf(h1[i], w, g1[j]);
            }
        ull gb0[4], gb1[4];
#pragma unroll
        for (int j = 0; j < 4; j++) {
            float gv0 = g0[j] + fabsf(g0[j]);
            float gv1 = g1[j] + fabsf(g1[j]);
            gb0[j] = pk(gv0, gv0);
            gb1[j] = pk(gv1, gv1);
        }

        // layer 3 + cosine for both patches, interleaved, constant port
        ull d0 = 0ULL, n0 = 0ULL, d1 = 0ULL, n1 = 0ULL;
#pragma unroll
        for (int i = 0; i < 8; i++) {
            ull y0 = b3p[i];
            ull y1 = y0;
#pragma unroll
            for (int j = 0; j < 4; j++) {
                ull w = W3p[j * 8 + i];
                y0 = fma2(gb0[j], w, y0);
                y1 = fma2(gb1[j], w, y1);
            }
            y0 = add2(y0, y0 & 0x7FFFFFFF7FFFFFFFULL);   // 2*relu
            y1 = add2(y1, y1 & 0x7FFFFFFF7FFFFFFFULL);
            ull x0 = (i & 1) ? B[i >> 1] : A[i >> 1];    // P0 pair i
            ull x1 = (i & 1) ? C[i >> 1] : B[i >> 1];    // P1 pair i
            d0 = fma2(x0, y0, d0);        // = 2*dot
            n0 = fma2(y0, y0, n0);        // = 4*ny2
            d1 = fma2(x1, y1, d1);
            n1 = fma2(y1, y1, n1);
        }
        // single rsqrt per patch: 2d * rsqrt(nx_c * 4ny_c) = d / sqrt(nx_c*ny_c)
        float dl, dh, xl, xh, yl, yh;
        upk(d0, dl, dh); upk(nx0p, xl, xh); upk(n0, yl, yh);
        float s0 = (dl + dh) * rsqrt_ap(fmaxf(xl + xh, 1e-16f) * fmaxf(yl + yh, 4e-16f));
        upk(d1, dl, dh); upk(nx1p, xl, xh); upk(n1, yl, yh);
        float s1 = (dl + dh) * rsqrt_ap(fmaxf(xl + xh, 1e-16f) * fmaxf(yl + yh, 4e-16f));

        float2 sv = make_float2(v0 ? s0 : 0.0f, v1 ? s1 : 0.0f);
        *reinterpret_cast<float2*>(sim + pyy * SIMW + 2 * pxp) = sv;
    }
    __syncthreads();

    // ---- fold: each thread handles 2x2 cells -> 4x4 output pixels
    const int tx = t & 15;
    const int ty = t >> 4;
    float* outb = out + (size_t)bt * (IMG * IMG);
#pragma unroll
    for (int dy = 0; dy < 2; dy++) {
        int ca = 2 * ty + dy;          // local cell row 0..31
        int a  = a0 + ca;              // global cell row 0..255
        int cb = 2 * tx;               // local cell col (left of pair)
        const float* s0 = sim + ca * SIMW + cb;
        const float* s1 = s0 + SIMW;
        float p00 = s0[0], p01 = s0[1], p02 = s0[2];
        float p10 = s1[0], p11 = s1[1], p12 = s1[2];
        float sumL = (p00 + p01) + (p10 + p11);
        float sumR = (p01 + p02) + (p11 + p12);
        int bL = b0 + cb, bR = bL + 1;
        float invy = (a == 0 || a == 255) ? 1.0f : 0.5f;
        float invL = (bL == 0 || bL == 255) ? 1.0f : 0.5f;
        float invR = (bR == 255) ? 1.0f : 0.5f;
        float vL = sumL * (invy * invL);
        float vR = sumR * (invy * invR);
        float4 v4 = make_float4(vL, vL, vR, vR);
        float* op = outb + (size_t)(2 * a) * IMG + 2 * bL;
        *reinterpret_cast<float4*>(op) = v4;
        *reinterpret_cast<float4*>(op + IMG) = v4;
    }
}

extern "C" void kernel_launch(void* const* d_in, const int* in_sizes, int n_in,
                              void* d_out, int out_size) {
    const float* img = (const float*)d_in[0];
    float* out = (float*)d_out;

    prep_kernel<<<1, 192>>>((const float*)d_in[1], (const float*)d_in[2],
                            (const float*)d_in[3], (const float*)d_in[4],
                            (const float*)d_in[5], (const float*)d_in[6]);
    void* src = nullptr;
    cudaGetSymbolAddress(&src, g_stage);
    cudaMemcpyToSymbolAsync(cbuf, src, 172 * sizeof(float), 0, cudaMemcpyDeviceToDevice);

    dim3 grid(IMG / (2 * TC), IMG / (2 * TC), BS);   // 8 x 8 x 32
    fused_kernel<<<grid, 256>>>(img, out);
}

// round 17
// speedup vs baseline: 1.1289x; 1.1289x over previous
#include <cuda_runtime.h>
#include <math.h>

#define IMG 512
#define BS  32
#define OH  255
#define OW  255
#define TC  32      // cells per tile dim (tile = 64x64 output pixels)
#define NPY 33      // patch rows per tile
#define NPXP 17     // horizontal patch PAIRS per tile
#define NUNIT (NPY * NPXP)   // 561
#define SIMW 34     // sim row stride (even -> float2 stores aligned)
#define NTHREADS 288

typedef unsigned long long ull;

// packed/pre-scaled weights; prep_kernel writes the backing store directly
// (address obtained host-side via cudaGetSymbolAddress), saving the staging
// buffer + memcpy graph node. Constant cache is invalidated at launch
// boundaries, and prep -> fused is stream-ordered, so reads are coherent.
__constant__ __align__(8) float cbuf[172];

// Layout (float offsets):
//   0: W1p  (32 float2) [q*4+j] = (W1[2q][j],   W1[2q+1][j])
//  64: b1p  ( 4 float2) [j]     = (b1[j], 0)
//  72: W2s  (16 float ) 0.5*W2
//  88: b2   ( 4 float )
//  92: W3p  (32 float2) [j*8+i] = 0.5*(W3[j][2i], W3[j][2i+1])
// 156: b3p  ( 8 float2) [i]     = (b3[2i], b3[2i+1])
__global__ void prep_kernel(float* __restrict__ dst,
                            const float* __restrict__ W1, const float* __restrict__ b1,
                            const float* __restrict__ W2, const float* __restrict__ b2,
                            const float* __restrict__ W3, const float* __restrict__ b3) {
    int f = threadIdx.x;
    if (f >= 172) return;
    float v;
    if (f < 64) {
        int q = f >> 1, lane = f & 1;
        int p = q >> 2, j = q & 3;
        v = W1[(2 * p + lane) * 4 + j];
    } else if (f < 72) {
        int q = (f - 64) >> 1, lane = f & 1;
        v = lane ? 0.0f : b1[q];
    } else if (f < 88) {
        v = 0.5f * W2[f - 72];
    } else if (f < 92) {
        v = b2[f - 88];
    } else if (f < 156) {
        int q = (f - 92) >> 1, lane = f & 1;
        int j = q >> 3, i = q & 7;
        v = 0.5f * W3[j * 16 + 2 * i + lane];
    } else {
        int q = (f - 156) >> 1, lane = f & 1;
        v = b3[2 * q + lane];
    }
    dst[f] = v;
}

__device__ __forceinline__ ull pk(float lo, float hi) {
    ull r; asm("mov.b64 %0, {%1, %2};" : "=l"(r) : "f"(lo), "f"(hi)); return r;
}
__device__ __forceinline__ void upk(ull v, float& lo, float& hi) {
    asm("mov.b64 {%0, %1}, %2;" : "=f"(lo), "=f"(hi) : "l"(v));
}
__device__ __forceinline__ ull fma2(ull a, ull b, ull c) {
    ull d; asm("fma.rn.f32x2 %0, %1, %2, %3;" : "=l"(d) : "l"(a), "l"(b), "l"(c)); return d;
}
__device__ __forceinline__ ull add2(ull a, ull b) {
    ull d; asm("add.rn.f32x2 %0, %1, %2;" : "=l"(d) : "l"(a), "l"(b)); return d;
}
// single-instruction MUFU.RSQ (operands clamped well inside range; ~2^-22 rel err)
__device__ __forceinline__ float rsqrt_ap(float x) {
    float y; asm("rsqrt.approx.f32 %0, %1;" : "=f"(y) : "f"(x)); return y;
}

__global__ __launch_bounds__(NTHREADS, 3)
void fused_kernel(const float* __restrict__ img, float* __restrict__ out) {
    __shared__ float sim[NPY * SIMW];   // 33 rows x 34 floats

    const int t  = threadIdx.x;
    const int b0 = blockIdx.x * TC;
    const int a0 = blockIdx.y * TC;
    const int bt = blockIdx.z;
    const float* imgb = img + (size_t)bt * (IMG * IMG);
    const ull* imgu = reinterpret_cast<const ull*>(imgb);

    const ull* W1p = reinterpret_cast<const ull*>(cbuf);
    const ull* b1p = reinterpret_cast<const ull*>(cbuf + 64);
    const float* W2s = cbuf + 72;
    const float* b2  = cbuf + 88;
    const ull* W3p = reinterpret_cast<const ull*>(cbuf + 92);
    const ull* b3p = reinterpret_cast<const ull*>(cbuf + 156);

    // ---- patch-PAIR phase: 561 units over 288 threads = 2 balanced rounds
    for (int u = t; u < NUNIT; u += NTHREADS) {
        const int pyy = u / NPXP;            // 0..32
        const int pxp = u - pyy * NPXP;      // 0..16
        const int oy  = a0 - 1 + pyy;
        const int ox0 = b0 - 1 + 2 * pxp;    // left patch col; right = ox0+1

        const int ry = min(max(oy, 0), OH - 1);
        const int ua = min(max(ox0, 0), 255);
        const int ub = min(ox0 + 1, 255);
        const int uc = min(ox0 + 2, 255);
        const bool v0 = ((unsigned)oy < OH) & ((unsigned)ox0 < OW);
        const bool v1 = ((unsigned)oy < OH) & ((unsigned)(ox0 + 1) < OW);

        const ull* row = imgu + (size_t)(2 * ry) * (IMG / 2);
        ull A[4], B[4], C[4];                // strips: P0=(A,B), P1=(B,C)
#pragma unroll
        for (int r = 0; r < 4; r++) {
            const ull* rp = row + (size_t)r * (IMG / 2);
            A[r] = __ldg(rp + ua);
            B[r] = __ldg(rp + ub);
            C[r] = __ldg(rp + uc);
        }

        // nx2 for both patches; middle strip squared once
        ull na = 0ULL, nb = 0ULL, nc = 0ULL;
#pragma unroll
        for (int r = 0; r < 4; r++) {
            na = fma2(A[r], A[r], na);
            nb = fma2(B[r], B[r], nb);
            nc = fma2(C[r], C[r], nc);
        }
        const ull nx0p = add2(na, nb);
        const ull nx1p = add2(nb, nc);

        // layer 1 for both patches, weights fetched once
        ull acc0[4], acc1[4];
#pragma unroll
        for (int j = 0; j < 4; j++) { acc0[j] = b1p[j]; acc1[j] = b1p[j]; }
#pragma unroll
        for (int r = 0; r < 4; r++) {
#pragma unroll
            for (int j = 0; j < 4; j++) {
                ull wL = W1p[(2 * r) * 4 + j];
                ull wR = W1p[(2 * r + 1) * 4 + j];
                acc0[j] = fma2(A[r], wL, acc0[j]);
                acc0[j] = fma2(B[r], wR, acc0[j]);
                acc1[j] = fma2(B[r], wL, acc1[j]);
                acc1[j] = fma2(C[r], wR, acc1[j]);
            }
        }
        float h0[4], h1[4];
#pragma unroll
        for (int j = 0; j < 4; j++) {
            float lo, hi;
            upk(acc0[j], lo, hi); float s0v = lo + hi; h0[j] = s0v + fabsf(s0v);
            upk(acc1[j], lo, hi); float s1v = lo + hi; h1[j] = s1v + fabsf(s1v);
        }

        // layer 2 for both patches (W2s = 0.5*W2), shared weight fetches
        float g0[4], g1[4];
#pragma unroll
        for (int j = 0; j < 4; j++) { g0[j] = b2[j]; g1[j] = b2[j]; }
#pragma unroll
        for (int i = 0; i < 4; i++)
#pragma unroll
            for (int j = 0; j < 4; j++) {
                float w = W2s[i * 4 + j];
                g0[j] = fmaf(h0[i], w, g0[j]);
                g1[j] = fmaf(h1[i], w, g1[j]);
            }
        ull gb0[4], gb1[4];
#pragma unroll
        for (int j = 0; j < 4; j++) {
            float gv0 = g0[j] + fabsf(g0[j]);
            float gv1 = g1[j] + fabsf(g1[j]);
            gb0[j] = pk(gv0, gv0);
            gb1[j] = pk(gv1, gv1);
        }

        // layer 3 + cosine for both patches, interleaved, shared weights;
        // both accumulator chains seed from the same LDC (no copy movs)
        ull d0 = 0ULL, n0 = 0ULL, d1 = 0ULL, n1 = 0ULL;
#pragma unroll
        for (int i = 0; i < 8; i++) {
            ull y0 = b3p[i];
            ull y1 = b3p[i];
#pragma unroll
            for (int j = 0; j < 4; j++) {
                ull w = W3p[j * 8 + i];
                y0 = fma2(gb0[j], w, y0);
                y1 = fma2(gb1[j], w, y1);
            }
            y0 = add2(y0, y0 & 0x7FFFFFFF7FFFFFFFULL);   // 2*relu
            y1 = add2(y1, y1 & 0x7FFFFFFF7FFFFFFFULL);
            ull x0 = (i & 1) ? B[i >> 1] : A[i >> 1];    // P0 pair i
            ull x1 = (i & 1) ? C[i >> 1] : B[i >> 1];    // P1 pair i
            d0 = fma2(x0, y0, d0);        // = 2*dot
            n0 = fma2(y0, y0, n0);        // = 4*ny2
            d1 = fma2(x1, y1, d1);
            n1 = fma2(y1, y1, n1);
        }
        // single rsqrt per patch: 2d * rsqrt(nx_c * 4ny_c) = d / sqrt(nx_c*ny_c)
        float dl, dh, xl, xh, yl, yh;
        upk(d0, dl, dh); upk(nx0p, xl, xh); upk(n0, yl, yh);
        float s0 = (dl + dh) * rsqrt_ap(fmaxf(xl + xh, 1e-16f) * fmaxf(yl + yh, 4e-16f));
        upk(d1, dl, dh); upk(nx1p, xl, xh); upk(n1, yl, yh);
        float s1 = (dl + dh) * rsqrt_ap(fmaxf(xl + xh, 1e-16f) * fmaxf(yl + yh, 4e-16f));

        float2 sv = make_float2(v0 ? s0 : 0.0f, v1 ? s1 : 0.0f);
        *reinterpret_cast<float2*>(sim + pyy * SIMW + 2 * pxp) = sv;
    }
    __syncthreads();

    // ---- fold (first 256 threads): 2x2 cells -> 4x4 output pixels each
    if (t < 256) {
        const int tx = t & 15;
        const int ty = t >> 4;
        float* outb = out + (size_t)bt * (IMG * IMG);
#pragma unroll
        for (int dy = 0; dy < 2; dy++) {
            int ca = 2 * ty + dy;          // local cell row 0..31
            int a  = a0 + ca;              // global cell row 0..255
            int cb = 2 * tx;               // local cell col (left of pair)
            const float* s0 = sim + ca * SIMW + cb;
            const float* s1 = s0 + SIMW;
            float p00 = s0[0], p01 = s0[1], p02 = s0[2];
            float p10 = s1[0], p11 = s1[1], p12 = s1[2];
            float sumL = (p00 + p01) + (p10 + p11);
            float sumR = (p01 + p02) + (p11 + p12);
            int bL = b0 + cb, bR = bL + 1;
            float invy = (a == 0 || a == 255) ? 1.0f : 0.5f;
            float invL = (bL == 0 || bL == 255) ? 1.0f : 0.5f;
            float invR = (bR == 255) ? 1.0f : 0.5f;
            float vL = sumL * (invy * invL);
            float vR = sumR * (invy * invR);
            float4 v4 = make_float4(vL, vL, vR, vR);
            float* op = outb + (size_t)(2 * a) * IMG + 2 * bL;
            *reinterpret_cast<float4*>(op) = v4;
            *reinterpret_cast<float4*>(op + IMG) = v4;
        }
    }
}

extern "C" void kernel_launch(void* const* d_in, const int* in_sizes, int n_in,
                              void* d_out, int out_size) {
    const float* img = (const float*)d_in[0];
    float* out = (float*)d_out;

    // prep writes the constant backing store directly (no staging, no memcpy)
    void* cbuf_dev = nullptr;
    cudaGetSymbolAddress(&cbuf_dev, cbuf);
    prep_kernel<<<1, 192>>>((float*)cbuf_dev,
                            (const float*)d_in[1], (const float*)d_in[2],
                            (const float*)d_in[3], (const float*)d_in[4],
                            (const float*)d_in[5], (const float*)d_in[6]);

    dim3 grid(IMG / (2 * TC), IMG / (2 * TC), BS);   // 8 x 8 x 32
    fused_kernel<<<grid, NTHREADS>>>(img, out);
}